// round 3
// baseline (speedup 1.0000x reference)
#include <cuda_runtime.h>

// Fixed shapes: B=64, C=3, H=W=256
#define NCAT    5
#define NB      64
#define E_ELEM  196608
#define E4      49152           // float4 positions per sample
#define TPB     256             // threads per block (4 subs x 64 positions)
#define NBLOCKS (E4 / 64)       // 768 blocks, 64 float4 positions each
#define NPART   15              // 5 scaled, 5 abs, 5 un-total
#define NPAD    16
#define EPSF    1e-6f

__device__ float g_part[NBLOCKS * NPAD];
__device__ int   g_done = 0;    // self-resetting last-block counter

// -------- packed f32x2 helpers (Blackwell) ---------------------------------
__device__ __forceinline__ unsigned long long f2_add(unsigned long long a, unsigned long long b) {
    unsigned long long r;
    asm("add.rn.f32x2 %0, %1, %2;" : "=l"(r) : "l"(a), "l"(b));
    return r;
}
__device__ __forceinline__ unsigned long long f2_fma(unsigned long long a, unsigned long long b,
                                                     unsigned long long c) {
    unsigned long long r;
    asm("fma.rn.f32x2 %0, %1, %2, %3;" : "=l"(r) : "l"(a), "l"(b), "l"(c));
    return r;
}
__device__ __forceinline__ void f2_unpack(unsigned long long v, float& lo, float& hi) {
    asm("mov.b64 {%0, %1}, %2;" : "=f"(lo), "=f"(hi) : "l"(v));
}
// butterfly-reduce a packed f32x2 pair across the 4 lanes of a quad
__device__ __forceinline__ unsigned long long quad_f2_sum(unsigned long long v) {
    v = f2_add(v, __shfl_xor_sync(0xffffffffu, v, 1));
    v = f2_add(v, __shfl_xor_sync(0xffffffffu, v, 2));
    return v;
}

#define NEG1X2 0xBF800000BF800000ULL   // packed (-1.0f, -1.0f)
#define ABSM2  0x7FFFFFFF7FFFFFFFULL   // packed abs mask

// ---------------------------------------------------------------------------
// Single fused kernel. Quad-split sample loop: lanes 4k..4k+3 share one float4
// position j; each takes every 4th sample; quad shuffle recovers full U/A.
// ---------------------------------------------------------------------------
__global__ void __launch_bounds__(TPB)
k_fused(const float* __restrict__ restored,
        const float* __restrict__ clean,
        const int*   __restrict__ de_id,
        const float* __restrict__ un,
        float*       __restrict__ out) {
    __shared__ int   s_id[NB];
    __shared__ int   s_off[NB];
    __shared__ int   s_start[NCAT + 1];
    __shared__ int   s_cnt[NCAT];
    __shared__ float s_invc[NCAT];
    __shared__ float sred[NPART][TPB];
    __shared__ int   s_last;

    const int tid = threadIdx.x;
    const int sub = tid & 3;            // which quarter of the samples
    const int j   = blockIdx.x * 64 + (tid >> 2);   // float4 position

    // ---- per-block setup: categorize + counting-sort 64 samples ----
    if (tid < NB) s_id[tid] = de_id[tid];
    __syncthreads();
    if (tid == 0) {
        int cnt[NCAT];
#pragma unroll
        for (int c = 0; c < NCAT; ++c) cnt[c] = 0;
#pragma unroll
        for (int b = 0; b < NB; ++b) {
            int c = s_id[b];
            c = c < 0 ? 0 : (c >= NCAT ? NCAT - 1 : c);
            s_id[b] = c;
            cnt[c]++;
        }
        int st = 0;
#pragma unroll
        for (int c = 0; c < NCAT; ++c) {
            s_start[c] = st;
            s_cnt[c]   = cnt[c];
            s_invc[c]  = 1.0f / (float)(cnt[c] > 0 ? cnt[c] : 1);
            st += cnt[c];
        }
        s_start[NCAT] = st;
        int pos[NCAT];
#pragma unroll
        for (int c = 0; c < NCAT; ++c) pos[c] = s_start[c];
#pragma unroll
        for (int b = 0; b < NB; ++b) s_off[pos[s_id[b]]++] = b * E4;
    }
    __syncthreads();

    const ulonglong2* __restrict__ rp = reinterpret_cast<const ulonglong2*>(restored);
    const ulonglong2* __restrict__ cp = reinterpret_cast<const ulonglong2*>(clean);
    const ulonglong2* __restrict__ up = reinterpret_cast<const ulonglong2*>(un);

    float vals[NPART];
    const bool lead = (sub == 0);

#pragma unroll 1
    for (int c = 0; c < NCAT; ++c) {
        unsigned long long U0 = 0ull, U1 = 0ull;
        unsigned long long A0 = 0ull, A1 = 0ull;
        const int ke = s_start[c + 1];
        int k = s_start[c] + sub;
#pragma unroll 2
        for (; k < ke; k += 4) {
            int off = s_off[k] + j;
            ulonglong2 u  = up[off];
            ulonglong2 r  = rp[off];
            ulonglong2 cl = cp[off];
            U0 = f2_add(U0, u.x);
            U1 = f2_add(U1, u.y);
            unsigned long long d0 = f2_fma(r.x, NEG1X2, cl.x) & ABSM2;
            unsigned long long d1 = f2_fma(r.y, NEG1X2, cl.y) & ABSM2;
            A0 = f2_add(A0, d0);
            A1 = f2_add(A1, d1);
        }
        // recover full per-position sums across the quad
        U0 = quad_f2_sum(U0);  U1 = quad_f2_sum(U1);
        A0 = quad_f2_sum(A0);  A1 = quad_f2_sum(A1);

        float u0, u1, u2, u3, a0, a1, a2, a3;
        f2_unpack(U0, u0, u1);  f2_unpack(U1, u2, u3);
        f2_unpack(A0, a0, a1);  f2_unpack(A1, a2, a3);
        float ic = s_invc[c];
        float s0 = 1.0f / (u0 * ic + EPSF);
        float s1 = 1.0f / (u1 * ic + EPSF);
        float s2 = 1.0f / (u2 * ic + EPSF);
        float s3 = 1.0f / (u3 * ic + EPSF);
        float vsc = fmaf(a3, s3, fmaf(a2, s2, fmaf(a1, s1, a0 * s0)));
        float vab = (a0 + a1) + (a2 + a3);
        float vun = (u0 + u1) + (u2 + u3);
        // only the quad leader contributes (others would quadruple-count)
        vals[c]      = lead ? vsc : 0.0f;
        vals[5 + c]  = lead ? vab : 0.0f;
        vals[10 + c] = lead ? vun : 0.0f;
    }

    // ---- block reduction of 15 values ----
#pragma unroll
    for (int v = 0; v < NPART; ++v) sred[v][tid] = vals[v];
    __syncthreads();
#pragma unroll
    for (int st = TPB / 2; st > 0; st >>= 1) {
        if (tid < st) {
#pragma unroll
            for (int v = 0; v < NPART; ++v) sred[v][tid] += sred[v][tid + st];
        }
        __syncthreads();
    }
    if (tid < NPART) g_part[blockIdx.x * NPAD + tid] = sred[tid][0];

    // ---- last-block finalize (deterministic fixed-order reads) ----
    __syncthreads();
    __threadfence();
    if (tid == 0) s_last = (atomicAdd(&g_done, 1) == NBLOCKS - 1);
    __syncthreads();
    if (!s_last) return;

    __threadfence();
    {
        // 768 rows / 256 threads = 3 rows each (NPAD=16 floats = 4 float4)
        float acc[NPART];
#pragma unroll
        for (int v = 0; v < NPART; ++v) acc[v] = 0.0f;
        const float4* gp4 = reinterpret_cast<const float4*>(g_part);
        int base = tid * 3 * (NPAD / 4);
#pragma unroll
        for (int r = 0; r < 3; ++r) {
            float4 q0 = __ldcg(gp4 + base + 0);
            float4 q1 = __ldcg(gp4 + base + 1);
            float4 q2 = __ldcg(gp4 + base + 2);
            float4 q3 = __ldcg(gp4 + base + 3);
            base += NPAD / 4;
            acc[0] += q0.x;  acc[1] += q0.y;  acc[2]  += q0.z;  acc[3]  += q0.w;
            acc[4] += q1.x;  acc[5] += q1.y;  acc[6]  += q1.z;  acc[7]  += q1.w;
            acc[8] += q2.x;  acc[9] += q2.y;  acc[10] += q2.z;  acc[11] += q2.w;
            acc[12] += q3.x; acc[13] += q3.y; acc[14] += q3.z;
        }
#pragma unroll
        for (int v = 0; v < NPART; ++v) sred[v][tid] = acc[v];
        __syncthreads();
#pragma unroll
        for (int st = TPB / 2; st > 0; st >>= 1) {
            if (tid < st) {
#pragma unroll
                for (int v = 0; v < NPART; ++v) sred[v][tid] += sred[v][tid + st];
            }
            __syncthreads();
        }
        if (tid == 0) {
            const float Ef = (float)E_ELEM;
            float totalsum = 0.0f, cum_sc = 0.0f, cumN = 0.0f;
            int num_ne = 0;
#pragma unroll
            for (int c = 0; c < NCAT; ++c) if (s_cnt[c] > 0) num_ne++;
#pragma unroll
            for (int c = 0; c < NCAT; ++c) {
                int   cnt  = s_cnt[c];
                bool  ne   = cnt > 0;
                float safe = (float)(cnt > 0 ? cnt : 1);
                float S_sc = sred[c][0];
                float S_ab = sred[5 + c][0];
                float S_un = sred[10 + c][0];

                cum_sc += S_sc;
                cumN   += (float)cnt * Ef;
                float cum_l1 = cum_sc / fmaxf(cumN, 1.0f);
                float un_num = S_un / (safe * Ef) + EPSF;
                float bn     = ne ? 2.0f * logf(un_num) : 0.0f;
                float unc    = ne ? cum_l1 : 0.0f;
                float old_l  = ne ? S_ab / (safe * Ef) : 0.0f;
                float cat_l  = unc + bn;
                totalsum += cat_l;

                out[1 + c]  = cat_l;
                out[6 + c]  = old_l;
                out[11 + c] = bn;
                out[16 + c] = unc;
            }
            out[0] = totalsum / (float)(num_ne > 0 ? num_ne : 1);
            g_done = 0;   // self-reset for graph replay
        }
    }
}

// ---------------------------------------------------------------------------
extern "C" void kernel_launch(void* const* d_in, const int* in_sizes, int n_in,
                              void* d_out, int out_size) {
    const float* restored = (const float*)d_in[0];
    const float* clean    = (const float*)d_in[1];
    const int*   de_id    = (const int*)d_in[2];
    const float* un       = (const float*)d_in[3];
    float*       out      = (float*)d_out;

    k_fused<<<NBLOCKS, TPB>>>(restored, clean, de_id, un, out);
}

// round 4
// speedup vs baseline: 1.2893x; 1.2893x over previous
#include <cuda_runtime.h>

// Fixed shapes: B=64, C=3, H=W=256
#define NCAT    5
#define NB      64
#define E_ELEM  196608
#define E4      49152            // float4 positions per sample
#define TPB     256
#define JBLK    192              // j-chunks: 192 * 256 = 49152
#define GRID    (NCAT * JBLK)    // 960 blocks
#define EPSF    1e-6f

__device__ ulonglong2 g_un_sum[NCAT * E4];   // U[c][j] packed f32x2 pairs (~3.9MB)
__device__ int        g_order[NB];           // sample offsets (b*E4), sorted by cat
__device__ int        g_start[NCAT + 1];
__device__ int        g_cnt[NCAT];
__device__ float      g_invc[NCAT];
__device__ float4     g_part[GRID];          // per-block (scaled, abs, un, 0)
__device__ int        g_done = 0;

// -------- packed f32x2 helpers ----------------------------------------------
__device__ __forceinline__ unsigned long long f2_add(unsigned long long a, unsigned long long b) {
    unsigned long long r;
    asm("add.rn.f32x2 %0, %1, %2;" : "=l"(r) : "l"(a), "l"(b));
    return r;
}
__device__ __forceinline__ unsigned long long f2_fma(unsigned long long a, unsigned long long b,
                                                     unsigned long long c) {
    unsigned long long r;
    asm("fma.rn.f32x2 %0, %1, %2, %3;" : "=l"(r) : "l"(a), "l"(b), "l"(c));
    return r;
}
__device__ __forceinline__ void f2_unpack(unsigned long long v, float& lo, float& hi) {
    asm("mov.b64 {%0, %1}, %2;" : "=f"(lo), "=f"(hi) : "l"(v));
}

#define NEG1X2 0xBF800000BF800000ULL
#define ABSM2  0x7FFFFFFF7FFFFFFFULL

// ---------------------------------------------------------------------------
// K0: counting-sort samples by category (tiny)
// ---------------------------------------------------------------------------
__global__ void k_setup(const int* __restrict__ de_id) {
    if (threadIdx.x != 0) return;
    int cat[NB], cnt[NCAT];
#pragma unroll
    for (int c = 0; c < NCAT; ++c) cnt[c] = 0;
#pragma unroll
    for (int b = 0; b < NB; ++b) {
        int c = de_id[b];
        c = c < 0 ? 0 : (c >= NCAT ? NCAT - 1 : c);
        cat[b] = c;
        cnt[c]++;
    }
    int st = 0;
#pragma unroll
    for (int c = 0; c < NCAT; ++c) {
        g_start[c] = st;
        g_cnt[c]   = cnt[c];
        g_invc[c]  = 1.0f / (float)(cnt[c] > 0 ? cnt[c] : 1);
        st += cnt[c];
    }
    g_start[NCAT] = st;
    int pos[NCAT];
#pragma unroll
    for (int c = 0; c < NCAT; ++c) pos[c] = g_start[c];
#pragma unroll
    for (int b = 0; b < NB; ++b) g_order[pos[cat[b]]++] = b * E4;
}

// ---------------------------------------------------------------------------
// K1: U[c][j] = sum of un over samples of category c. Thread = (c, j).
// ---------------------------------------------------------------------------
__global__ void __launch_bounds__(TPB)
k_unsum(const float* __restrict__ un) {
    __shared__ int s_off[NB];
    const int tid = threadIdx.x;
    const int c   = blockIdx.x / JBLK;
    const int jc  = blockIdx.x % JBLK;

    const int ks = g_start[c];
    const int n  = g_start[c + 1] - ks;
    if (tid < n) s_off[tid] = g_order[ks + tid];
    __syncthreads();

    const int j = jc * TPB + tid;
    const ulonglong2* __restrict__ up = reinterpret_cast<const ulonglong2*>(un);

    unsigned long long U0 = 0ull, U1 = 0ull;
#pragma unroll 4
    for (int k = 0; k < n; ++k) {
        ulonglong2 u = up[s_off[k] + j];
        U0 = f2_add(U0, u.x);
        U1 = f2_add(U1, u.y);
    }
    ulonglong2 o; o.x = U0; o.y = U1;
    g_un_sum[c * E4 + j] = o;
}

// ---------------------------------------------------------------------------
// K2: per-(c,j) abs-diff sums, scale-dot at flush, block reduce, finalize.
// ---------------------------------------------------------------------------
__global__ void __launch_bounds__(TPB)
k_main(const float* __restrict__ restored,
       const float* __restrict__ clean,
       float*       __restrict__ out) {
    __shared__ int   s_off[NB];
    __shared__ float sred[3][TPB];
    __shared__ int   s_last;

    const int tid = threadIdx.x;
    const int c   = blockIdx.x / JBLK;
    const int jc  = blockIdx.x % JBLK;

    const int ks = g_start[c];
    const int n  = g_start[c + 1] - ks;
    if (tid < n) s_off[tid] = g_order[ks + tid];
    __syncthreads();

    const int j = jc * TPB + tid;
    const ulonglong2* __restrict__ rp = reinterpret_cast<const ulonglong2*>(restored);
    const ulonglong2* __restrict__ cp = reinterpret_cast<const ulonglong2*>(clean);

    unsigned long long A0 = 0ull, A1 = 0ull;
#pragma unroll 4
    for (int k = 0; k < n; ++k) {
        int off = s_off[k] + j;
        ulonglong2 r  = rp[off];
        ulonglong2 cl = cp[off];
        A0 = f2_add(A0, f2_fma(r.x, NEG1X2, cl.x) & ABSM2);
        A1 = f2_add(A1, f2_fma(r.y, NEG1X2, cl.y) & ABSM2);
    }

    // flush: load U for (c,j), build s, dot with A
    ulonglong2 uu = g_un_sum[c * E4 + j];
    float u0, u1, u2, u3, a0, a1, a2, a3;
    f2_unpack(uu.x, u0, u1);  f2_unpack(uu.y, u2, u3);
    f2_unpack(A0, a0, a1);    f2_unpack(A1, a2, a3);
    const float ic = g_invc[c];
    float s0 = 1.0f / (u0 * ic + EPSF);
    float s1 = 1.0f / (u1 * ic + EPSF);
    float s2 = 1.0f / (u2 * ic + EPSF);
    float s3 = 1.0f / (u3 * ic + EPSF);

    sred[0][tid] = fmaf(a3, s3, fmaf(a2, s2, fmaf(a1, s1, a0 * s0)));  // scaled
    sred[1][tid] = (a0 + a1) + (a2 + a3);                               // abs
    sred[2][tid] = (u0 + u1) + (u2 + u3);                               // un total
    __syncthreads();
#pragma unroll
    for (int st = TPB / 2; st > 0; st >>= 1) {
        if (tid < st) {
            sred[0][tid] += sred[0][tid + st];
            sred[1][tid] += sred[1][tid + st];
            sred[2][tid] += sred[2][tid + st];
        }
        __syncthreads();
    }
    if (tid == 0) {
        float4 q; q.x = sred[0][0]; q.y = sred[1][0]; q.z = sred[2][0]; q.w = 0.0f;
        g_part[blockIdx.x] = q;
    }

    // ---- last-block finalize ----
    __threadfence();
    __syncthreads();
    if (tid == 0) s_last = (atomicAdd(&g_done, 1) == GRID - 1);
    __syncthreads();
    if (!s_last) return;
    __threadfence();

    __shared__ float f_sc[NCAT][48], f_ab[NCAT][48], f_un[NCAT][48];
    if (tid < NCAT * 48) {                 // 240 threads
        int cc = tid / 48, g = tid % 48;
        float sc = 0.0f, ab = 0.0f, un = 0.0f;
#pragma unroll
        for (int r = 0; r < 4; ++r) {
            float4 q = __ldcg(&g_part[cc * JBLK + g * 4 + r]);
            sc += q.x; ab += q.y; un += q.z;
        }
        f_sc[cc][g] = sc; f_ab[cc][g] = ab; f_un[cc][g] = un;
    }
    __syncthreads();
    __shared__ float stot[3][NCAT];
    if (tid < NCAT) {
        float sc = 0.0f, ab = 0.0f, un = 0.0f;
#pragma unroll
        for (int g = 0; g < 48; ++g) { sc += f_sc[tid][g]; ab += f_ab[tid][g]; un += f_un[tid][g]; }
        stot[0][tid] = sc; stot[1][tid] = ab; stot[2][tid] = un;
    }
    __syncthreads();

    if (tid == 0) {
        const float Ef = (float)E_ELEM;
        float totalsum = 0.0f, cum_sc = 0.0f, cumN = 0.0f;
        int num_ne = 0;
#pragma unroll
        for (int cc = 0; cc < NCAT; ++cc) if (g_cnt[cc] > 0) num_ne++;
#pragma unroll
        for (int cc = 0; cc < NCAT; ++cc) {
            int   cnt  = g_cnt[cc];
            bool  ne   = cnt > 0;
            float safe = (float)(cnt > 0 ? cnt : 1);
            float S_sc = stot[0][cc];
            float S_ab = stot[1][cc];
            float S_un = stot[2][cc];

            cum_sc += S_sc;
            cumN   += (float)cnt * Ef;
            float cum_l1 = cum_sc / fmaxf(cumN, 1.0f);
            float un_num = S_un / (safe * Ef) + EPSF;
            float bn     = ne ? 2.0f * logf(un_num) : 0.0f;
            float unc    = ne ? cum_l1 : 0.0f;
            float old_l  = ne ? S_ab / (safe * Ef) : 0.0f;
            float cat_l  = unc + bn;
            totalsum += cat_l;

            out[1 + cc]  = cat_l;
            out[6 + cc]  = old_l;
            out[11 + cc] = bn;
            out[16 + cc] = unc;
        }
        out[0] = totalsum / (float)(num_ne > 0 ? num_ne : 1);
        g_done = 0;   // self-reset for graph replay
    }
}

// ---------------------------------------------------------------------------
extern "C" void kernel_launch(void* const* d_in, const int* in_sizes, int n_in,
                              void* d_out, int out_size) {
    const float* restored = (const float*)d_in[0];
    const float* clean    = (const float*)d_in[1];
    const int*   de_id    = (const int*)d_in[2];
    const float* un       = (const float*)d_in[3];
    float*       out      = (float*)d_out;

    k_setup<<<1, 32>>>(de_id);
    k_unsum<<<GRID, TPB>>>(un);
    k_main<<<GRID, TPB>>>(restored, clean, out);
}

// round 5
// speedup vs baseline: 1.4802x; 1.1480x over previous
#include <cuda_runtime.h>

// Fixed shapes: B=64, C=3, H=W=256
#define NCAT    5
#define NB      64
#define E_ELEM  196608
#define E4      49152            // float4 positions per sample
#define TPB     256
#define JBLK    192              // j-chunks: 192 * 256 = 49152
#define GRID    (NCAT * JBLK)    // 960 blocks
#define EPSF    1e-6f

__device__ float4 g_part[GRID];  // per-block (scaled, abs, un, 0)
__device__ int    g_done = 0;    // self-resetting last-block counter

// -------- packed f32x2 helpers ----------------------------------------------
__device__ __forceinline__ unsigned long long f2_add(unsigned long long a, unsigned long long b) {
    unsigned long long r;
    asm("add.rn.f32x2 %0, %1, %2;" : "=l"(r) : "l"(a), "l"(b));
    return r;
}
__device__ __forceinline__ unsigned long long f2_fma(unsigned long long a, unsigned long long b,
                                                     unsigned long long c) {
    unsigned long long r;
    asm("fma.rn.f32x2 %0, %1, %2, %3;" : "=l"(r) : "l"(a), "l"(b), "l"(c));
    return r;
}
__device__ __forceinline__ void f2_unpack(unsigned long long v, float& lo, float& hi) {
    asm("mov.b64 {%0, %1}, %2;" : "=f"(lo), "=f"(hi) : "l"(v));
}

#define NEG1X2 0xBF800000BF800000ULL
#define ABSM2  0x7FFFFFFF7FFFFFFFULL

// ---------------------------------------------------------------------------
// Single kernel. Block = (category c, j-chunk). Thread (c,j) accumulates BOTH
// U[c,j] (un-sum) and A[c,j] (|clean-restored| sum) over cat-c samples in one
// load stream, then flushes once: s = 1/(U/cnt+eps), dot with A.
// ---------------------------------------------------------------------------
__global__ void __launch_bounds__(TPB)
k_fused(const float* __restrict__ restored,
        const float* __restrict__ clean,
        const int*   __restrict__ de_id,
        const float* __restrict__ un,
        float*       __restrict__ out) {
    __shared__ int   s_id[NB];
    __shared__ int   s_off[NB];         // this category's sample offsets (b*E4)
    __shared__ int   s_cnt[NCAT];
    __shared__ int   s_n;
    __shared__ float s_ic;
    __shared__ float sred[3][TPB];
    __shared__ int   s_last;

    const int tid = threadIdx.x;
    const int c   = blockIdx.x / JBLK;
    const int jc  = blockIdx.x % JBLK;

    // ---- per-block setup: read 64 ids, collect this category's samples ----
    if (tid < NB) s_id[tid] = de_id[tid];
    __syncthreads();
    if (tid == 0) {
        int cnt[NCAT];
#pragma unroll
        for (int k = 0; k < NCAT; ++k) cnt[k] = 0;
        int n = 0;
#pragma unroll
        for (int b = 0; b < NB; ++b) {
            int cc = s_id[b];
            cc = cc < 0 ? 0 : (cc >= NCAT ? NCAT - 1 : cc);
            cnt[cc]++;
            if (cc == c) s_off[n++] = b * E4;
        }
#pragma unroll
        for (int k = 0; k < NCAT; ++k) s_cnt[k] = cnt[k];
        s_n  = n;
        s_ic = 1.0f / (float)(n > 0 ? n : 1);
    }
    __syncthreads();

    const int n = s_n;
    const int j = jc * TPB + tid;
    const ulonglong2* __restrict__ rp = reinterpret_cast<const ulonglong2*>(restored);
    const ulonglong2* __restrict__ cp = reinterpret_cast<const ulonglong2*>(clean);
    const ulonglong2* __restrict__ up = reinterpret_cast<const ulonglong2*>(un);

    unsigned long long U0 = 0ull, U1 = 0ull;
    unsigned long long A0 = 0ull, A1 = 0ull;
#pragma unroll 4
    for (int k = 0; k < n; ++k) {
        int off = s_off[k] + j;
        ulonglong2 u  = up[off];
        ulonglong2 r  = rp[off];
        ulonglong2 cl = cp[off];
        U0 = f2_add(U0, u.x);
        U1 = f2_add(U1, u.y);
        A0 = f2_add(A0, f2_fma(r.x, NEG1X2, cl.x) & ABSM2);
        A1 = f2_add(A1, f2_fma(r.y, NEG1X2, cl.y) & ABSM2);
    }

    // ---- flush: scale and dot ----
    float u0, u1, u2, u3, a0, a1, a2, a3;
    f2_unpack(U0, u0, u1);  f2_unpack(U1, u2, u3);
    f2_unpack(A0, a0, a1);  f2_unpack(A1, a2, a3);
    const float ic = s_ic;
    float s0 = 1.0f / (u0 * ic + EPSF);
    float s1 = 1.0f / (u1 * ic + EPSF);
    float s2 = 1.0f / (u2 * ic + EPSF);
    float s3 = 1.0f / (u3 * ic + EPSF);

    sred[0][tid] = fmaf(a3, s3, fmaf(a2, s2, fmaf(a1, s1, a0 * s0)));  // scaled
    sred[1][tid] = (a0 + a1) + (a2 + a3);                               // abs
    sred[2][tid] = (u0 + u1) + (u2 + u3);                               // un total
    __syncthreads();
#pragma unroll
    for (int st = TPB / 2; st > 0; st >>= 1) {
        if (tid < st) {
            sred[0][tid] += sred[0][tid + st];
            sred[1][tid] += sred[1][tid + st];
            sred[2][tid] += sred[2][tid + st];
        }
        __syncthreads();
    }
    if (tid == 0) {
        float4 q; q.x = sred[0][0]; q.y = sred[1][0]; q.z = sred[2][0]; q.w = 0.0f;
        g_part[blockIdx.x] = q;
    }

    // ---- last-block finalize (deterministic fixed-order reads) ----
    __threadfence();
    __syncthreads();
    if (tid == 0) s_last = (atomicAdd(&g_done, 1) == GRID - 1);
    __syncthreads();
    if (!s_last) return;
    __threadfence();

    __shared__ float f_sc[NCAT][48], f_ab[NCAT][48], f_un[NCAT][48];
    if (tid < NCAT * 48) {                 // 240 threads
        int cc = tid / 48, g = tid % 48;
        float sc = 0.0f, ab = 0.0f, uu = 0.0f;
#pragma unroll
        for (int r = 0; r < 4; ++r) {
            float4 q = __ldcg(&g_part[cc * JBLK + g * 4 + r]);
            sc += q.x; ab += q.y; uu += q.z;
        }
        f_sc[cc][g] = sc; f_ab[cc][g] = ab; f_un[cc][g] = uu;
    }
    __syncthreads();
    __shared__ float stot[3][NCAT];
    if (tid < NCAT) {
        float sc = 0.0f, ab = 0.0f, uu = 0.0f;
#pragma unroll
        for (int g = 0; g < 48; ++g) { sc += f_sc[tid][g]; ab += f_ab[tid][g]; uu += f_un[tid][g]; }
        stot[0][tid] = sc; stot[1][tid] = ab; stot[2][tid] = uu;
    }
    __syncthreads();

    if (tid == 0) {
        const float Ef = (float)E_ELEM;
        float totalsum = 0.0f, cum_sc = 0.0f, cumN = 0.0f;
        int num_ne = 0;
#pragma unroll
        for (int cc = 0; cc < NCAT; ++cc) if (s_cnt[cc] > 0) num_ne++;
#pragma unroll
        for (int cc = 0; cc < NCAT; ++cc) {
            int   cnt  = s_cnt[cc];
            bool  ne   = cnt > 0;
            float safe = (float)(cnt > 0 ? cnt : 1);
            float S_sc = stot[0][cc];
            float S_ab = stot[1][cc];
            float S_un = stot[2][cc];

            cum_sc += S_sc;
            cumN   += (float)cnt * Ef;
            float cum_l1 = cum_sc / fmaxf(cumN, 1.0f);
            float un_num = S_un / (safe * Ef) + EPSF;
            float bn     = ne ? 2.0f * logf(un_num) : 0.0f;
            float unc    = ne ? cum_l1 : 0.0f;
            float old_l  = ne ? S_ab / (safe * Ef) : 0.0f;
            float cat_l  = unc + bn;
            totalsum += cat_l;

            out[1 + cc]  = cat_l;
            out[6 + cc]  = old_l;
            out[11 + cc] = bn;
            out[16 + cc] = unc;
        }
        out[0] = totalsum / (float)(num_ne > 0 ? num_ne : 1);
        g_done = 0;   // self-reset for graph replay
    }
}

// ---------------------------------------------------------------------------
extern "C" void kernel_launch(void* const* d_in, const int* in_sizes, int n_in,
                              void* d_out, int out_size) {
    const float* restored = (const float*)d_in[0];
    const float* clean    = (const float*)d_in[1];
    const int*   de_id    = (const int*)d_in[2];
    const float* un       = (const float*)d_in[3];
    float*       out      = (float*)d_out;

    k_fused<<<GRID, TPB>>>(restored, clean, de_id, un, out);
}